// round 15
// baseline (speedup 1.0000x reference)
#include <cuda_runtime.h>
#include <math.h>

// Problem constants
#define T_STEPS 1024
#define BATCH   64
#define DIM     768      // D == N == 768
#define NB_CTA  128
#define NTHR    256

// -------- device-global scratch (allocation-free rule: __device__ arrays) ----
__device__ float g_xproj [(size_t)T_STEPS * 4 * BATCH * DIM];  // [t][g][b][n]
__device__ float g_WrT[(size_t)4 * DIM * DIM];                 // [g][n][k]
__device__ float g_hT[2][DIM * BATCH];                         // [n][b] ping-pong
__device__ float g_cT[DIM * BATCH];                            // [n][b]
__device__ unsigned int g_bar;

// ---------------------------------------------------------------------------
__global__ void init_state(const float* __restrict__ h0, const float* __restrict__ c0) {
    int i = blockIdx.x * blockDim.x + threadIdx.x;
    if (i == 0) g_bar = 0u;
    if (i < DIM * BATCH) {
        int n = i >> 6, bb = i & 63;
        g_hT[0][i] = h0[bb * DIM + n];
        g_cT[i]    = c0[bb * DIM + n];
    }
}

// ---------------------------------------------------------------------------
// transpose Wr[k][n] -> g_WrT[g][n][k].  grid (24, 24, 4), block (32, 8)
// ---------------------------------------------------------------------------
__global__ void transpose_wr(const float* __restrict__ w0, const float* __restrict__ w1,
                             const float* __restrict__ w2, const float* __restrict__ w3) {
    __shared__ float tile[32][33];
    int g = blockIdx.z;
    const float* W = (g == 0) ? w0 : (g == 1) ? w1 : (g == 2) ? w2 : w3;
    int n0 = blockIdx.x * 32;
    int k0 = blockIdx.y * 32;
    int tx = threadIdx.x, ty = threadIdx.y;

    #pragma unroll
    for (int i = ty; i < 32; i += 8)
        tile[i][tx] = W[(size_t)(k0 + i) * DIM + n0 + tx];
    __syncthreads();

    float* WT = g_WrT + (size_t)g * DIM * DIM;
    #pragma unroll
    for (int i = ty; i < 32; i += 8)
        WT[(size_t)(n0 + i) * DIM + k0 + tx] = tile[tx][i];
}

// ---------------------------------------------------------------------------
// FFMA2 helper (fma.rn.f32x2 — packed 2x fp32 FMA, PTX-only on sm_103a)
// ---------------------------------------------------------------------------
__device__ __forceinline__ void ffma2(unsigned long long& d,
                                      unsigned long long a, unsigned long long b) {
    asm("fma.rn.f32x2 %0, %1, %2, %0;" : "+l"(d) : "l"(a), "l"(b));
}

// ---------------------------------------------------------------------------
// Phase 1: input projections with FFMA2 (2 m-rows packed per accumulator).
// 128x128x8 tile, 256 threads. Thread microtile: 4 row-pairs x 8 cols, both
// strided by 16 so A/B smem reads are conflict-free.
// Output layout [t][g][b][n].
// grid (512, 6, 4)
// ---------------------------------------------------------------------------
__global__ __launch_bounds__(256) void input_proj(
        const float* __restrict__ x,
        const float* __restrict__ wk0, const float* __restrict__ wk1,
        const float* __restrict__ wk2, const float* __restrict__ wk3) {
    __shared__ __align__(16) float As[2][8][128];   // As[buf][k][m] (pairs = consecutive m)
    __shared__ __align__(16) float Bs[2][8][256];   // duplicated {w,w} per n

    int g = blockIdx.z;
    const float* W = (g == 0) ? wk0 : (g == 1) ? wk1 : (g == 2) ? wk2 : wk3;
    int m0 = blockIdx.x * 128;
    int n0 = blockIdx.y * 128;
    int tid = threadIdx.x;
    int tx = tid & 15;          // n base
    int ty = tid >> 4;          // row-pair base (0..15)

    int ar = tid >> 1, ak = (tid & 1) * 4;
    int bk = tid >> 5, bc = (tid & 31) * 4;

    const float* aptr = x + (size_t)(m0 + ar) * DIM + ak;
    const float* bptr = W + (size_t)bk * DIM + n0 + bc;

    float4 a = *(const float4*)(aptr);
    float4 b = *(const float4*)(bptr);
    As[0][ak + 0][ar] = a.x; As[0][ak + 1][ar] = a.y;
    As[0][ak + 2][ar] = a.z; As[0][ak + 3][ar] = a.w;
    *(float2*)&Bs[0][bk][2 * (bc + 0)] = make_float2(b.x, b.x);
    *(float2*)&Bs[0][bk][2 * (bc + 1)] = make_float2(b.y, b.y);
    *(float2*)&Bs[0][bk][2 * (bc + 2)] = make_float2(b.z, b.z);
    *(float2*)&Bs[0][bk][2 * (bc + 3)] = make_float2(b.w, b.w);
    __syncthreads();

    unsigned long long acc[4][8];
    #pragma unroll
    for (int i = 0; i < 4; ++i)
        #pragma unroll
        for (int j = 0; j < 8; ++j) acc[i][j] = 0ull;

    int buf = 0;
    for (int kt = 0; kt < 96; ++kt) {
        if (kt < 95) {
            int k0n = (kt + 1) * 8;
            a = *(const float4*)(aptr + k0n);
            b = *(const float4*)(bptr + (size_t)k0n * DIM);
        }
        #pragma unroll
        for (int kk = 0; kk < 8; ++kk) {
            unsigned long long a2[4], b2[8];
            #pragma unroll
            for (int i = 0; i < 4; ++i)
                a2[i] = *(const unsigned long long*)&As[buf][kk][2 * (ty + 16 * i)];
            #pragma unroll
            for (int j = 0; j < 8; ++j)
                b2[j] = *(const unsigned long long*)&Bs[buf][kk][2 * (tx + 16 * j)];
            #pragma unroll
            for (int i = 0; i < 4; ++i)
                #pragma unroll
                for (int j = 0; j < 8; ++j)
                    ffma2(acc[i][j], a2[i], b2[j]);
        }
        if (kt < 95) {
            __syncthreads();
            buf ^= 1;
            As[buf][ak + 0][ar] = a.x; As[buf][ak + 1][ar] = a.y;
            As[buf][ak + 2][ar] = a.z; As[buf][ak + 3][ar] = a.w;
            *(float2*)&Bs[buf][bk][2 * (bc + 0)] = make_float2(b.x, b.x);
            *(float2*)&Bs[buf][bk][2 * (bc + 1)] = make_float2(b.y, b.y);
            *(float2*)&Bs[buf][bk][2 * (bc + 2)] = make_float2(b.z, b.z);
            *(float2*)&Bs[buf][bk][2 * (bc + 3)] = make_float2(b.w, b.w);
            __syncthreads();
        }
    }

    // store: pair i -> rows m0+2*(ty+16i), +1 ; col j -> n0 + tx + 16j
    #pragma unroll
    for (int i = 0; i < 4; ++i) {
        int m_lo = m0 + 2 * (ty + 16 * i);
        int bb = m_lo >> 10;             // m = b*1024 + t
        int tt = m_lo & 1023;            // even; tt+1 stays in same b-block
        float* base_lo = g_xproj + ((size_t)((tt * 4 + g) * 64 + bb)) * DIM + n0;
        float* base_hi = g_xproj + ((size_t)(((tt + 1) * 4 + g) * 64 + bb)) * DIM + n0;
        #pragma unroll
        for (int j = 0; j < 8; ++j) {
            float lo, hi;
            asm("mov.b64 {%0,%1}, %2;" : "=f"(lo), "=f"(hi) : "l"(acc[i][j]));
            base_lo[tx + 16 * j] = lo;
            base_hi[tx + 16 * j] = hi;
        }
    }
}

// ---------------------------------------------------------------------------
// Phase 2: persistent recurrence. 128 CTAs x 256 threads, 1 CTA/SM.
// Thread tile: 4 batch-pairs (8 rows) x 6 cols (one gate's 6 n-cols),
// warp-level k-split by 8 (kk === warp_kp mod 8), reduced through smem.
// h kept in [n][b] layout globally -> slice staging is a straight copy.
// Weights duplicated {w,w} in smem for the whole kernel (col pad 770 f2).
// R15 change (the ONLY change vs the R14-passing artifact): x-projection is
// prefetched at step start DIRECTLY from g_xproj[t][g][b][n] (6 scalar __ldg
// per thread, hidden under the GEMM) -> transpose_x kernel and g_xprojT
// eliminated. Same values added in the same order -> bit-identical output.
// ---------------------------------------------------------------------------
#define WS_COL 770                                  // float2 per weight col (pad)
#define OFF_SCRATCH (24 * WS_COL * 2)               // 36960 floats
#define OFF_PRE     (OFF_SCRATCH + 16384)           // after 2x8192 H2 buffers
#define OFF_STASH   (OFF_PRE + 24 * 64)
#define SMEM_FLOATS (OFF_STASH + 64 * 9)
#define SMEM_BYTES  (SMEM_FLOATS * 4)               // 221824 B

__device__ __forceinline__ void grid_sync(unsigned int target) {
    __syncthreads();
    if (threadIdx.x == 0) {
        __threadfence();
        atomicAdd(&g_bar, 1u);
        while (atomicAdd(&g_bar, 0u) < target) { }
        __threadfence();
    }
    __syncthreads();
}

__global__ __launch_bounds__(NTHR, 1) void lstm_persistent(float* __restrict__ out) {
    extern __shared__ float smem[];
    float2* Ws2    = (float2*)smem;                  // [24][WS_COL] dup weights
    float* scratch = smem + OFF_SCRATCH;             // 2x H2 buffers / red alias
    float* pre     = smem + OFF_PRE;                 // [24][64] preactivations
    float* stash   = smem + OFF_STASH;               // [64][9] h for out-writes

    const int nb  = blockIdx.x;
    const int tid = threadIdx.x;
    const int rt  = tid & 7;            // batch-pair base (pairs rt+8j)
    const int ct  = (tid >> 3) & 3;     // gate (0..3)
    const int kp  = tid >> 5;           // k-partition == warp id (0..7)

    // ---- stage duplicated weights once (reused for all 1024 steps) ----
    for (int i = tid; i < 24 * 192; i += NTHR) {
        int c = i / 192, q = i - c * 192;
        int g = c / 6, nl = c - g * 6;
        float4 v = *(const float4*)(g_WrT + ((size_t)g * DIM + nb * 6 + nl) * DIM + q * 4);
        float2* dst = Ws2 + c * WS_COL + q * 4;
        dst[0] = make_float2(v.x, v.x);
        dst[1] = make_float2(v.y, v.y);
        dst[2] = make_float2(v.z, v.z);
        dst[3] = make_float2(v.w, v.w);
    }
    __syncthreads();

    const unsigned long long* wbase =
        (const unsigned long long*)(Ws2 + ct * 6 * WS_COL);

    for (int t = 0; t < T_STEPS; ++t) {
        const float* hT = g_hT[t & 1];

        // ---- prefetch x-projection directly from [t][g][b][n] ----
        // same (o, c, p) derivation as the reduction consumer below:
        // o = tid + u*NTHR; c = o>>5 (0..23); p = o&31 -> batches 2p, 2p+1
        float xs[3][2];
        #pragma unroll
        for (int u = 0; u < 3; ++u) {
            int o = tid + u * NTHR;
            int c = o >> 5, p = o & 31;
            int gg = c / 6, nl = c - gg * 6;
            const float* xp = g_xproj + ((size_t)((t * 4 + gg) * 64)) * DIM + nb * 6 + nl;
            xs[u][0] = __ldg(xp + (size_t)(2 * p) * DIM);
            xs[u][1] = __ldg(xp + (size_t)(2 * p + 1) * DIM);
        }

        unsigned long long acc[6][4];
        #pragma unroll
        for (int cj = 0; cj < 6; ++cj)
            #pragma unroll
            for (int pj = 0; pj < 4; ++pj) acc[cj][pj] = 0ull;

        // prologue: stage k-slice 0 (straight copy — hT is [n][b])
        {
            const float4* src = (const float4*)hT;
            float4* d = (float4*)scratch;
            #pragma unroll
            for (int q = 0; q < 8; ++q) d[q * NTHR + tid] = __ldcg(src + q * NTHR + tid);
        }
        __syncthreads();

        for (int kt = 0; kt < 6; ++kt) {
            float4 r[8];
            if (kt < 5) {
                const float4* src = (const float4*)(hT + (kt + 1) * 128 * 64);
                #pragma unroll
                for (int q = 0; q < 8; ++q) r[q] = __ldcg(src + q * NTHR + tid);
            }
            const unsigned long long* h2 =
                (const unsigned long long*)(scratch + (kt & 1) * 8192);
            const int k0 = kt * 128;
            #pragma unroll 4
            for (int m = 0; m < 16; ++m) {
                int kk = kp + (m << 3);
                unsigned long long hr[4];
                #pragma unroll
                for (int pj = 0; pj < 4; ++pj)
                    hr[pj] = h2[kk * 32 + rt + (pj << 3)];
                #pragma unroll
                for (int cj = 0; cj < 6; ++cj) {
                    unsigned long long w = wbase[cj * WS_COL + k0 + kk];
                    #pragma unroll
                    for (int pj = 0; pj < 4; ++pj) ffma2(acc[cj][pj], hr[pj], w);
                }
            }
            if (kt < 5) {
                float4* d = (float4*)(scratch + ((kt + 1) & 1) * 8192);
                #pragma unroll
                for (int q = 0; q < 8; ++q) d[q * NTHR + tid] = r[q];
            }
            __syncthreads();
        }

        // ---- k-partition reduction via smem (red aliases dead H2 buffers) ----
        float2* red = (float2*)scratch;              // [8][24][33]
        #pragma unroll
        for (int cj = 0; cj < 6; ++cj)
            #pragma unroll
            for (int pj = 0; pj < 4; ++pj) {
                float lo, hi;
                asm("mov.b64 {%0,%1}, %2;" : "=f"(lo), "=f"(hi) : "l"(acc[cj][pj]));
                red[kp * 792 + (ct * 6 + cj) * 33 + rt + (pj << 3)] = make_float2(lo, hi);
            }
        __syncthreads();

        #pragma unroll
        for (int u = 0; u < 3; ++u) {
            int o = tid + u * NTHR;                  // 0..767
            int c = o >> 5, p = o & 31;
            float2 s = red[c * 33 + p];
            #pragma unroll
            for (int k2 = 1; k2 < 8; ++k2) {
                float2 v = red[k2 * 792 + c * 33 + p];
                s.x += v.x; s.y += v.y;
            }
            s.x += xs[u][0];
            s.y += xs[u][1];
            *(float2*)(pre + c * 64 + 2 * p) = s;
        }
        __syncthreads();

        // ---- gate update: 64 batch x 6 n-cols (CTA-private slice) ----
        float* hTn = g_hT[(t + 1) & 1];
        for (int i = tid; i < 384; i += NTHR) {
            int bb = i & 63, j = i >> 6;
            float xi = pre[(0 * 6 + j) * 64 + bb];
            float xf = pre[(1 * 6 + j) * 64 + bb];
            float xg = pre[(2 * 6 + j) * 64 + bb];
            float xo = pre[(3 * 6 + j) * 64 + bb];
            int n = nb * 6 + j;
            float ii  = fminf(fmaxf(0.2f * xi + 0.5f, 0.f), 1.f);
            float ff  = fminf(fmaxf(0.2f * xf + 0.5f, 0.f), 1.f);
            float oo  = fminf(fmaxf(0.2f * xo + 0.5f, 0.f), 1.f);
            float gg2 = tanhf(xg);
            float cold = g_cT[n * 64 + bb];
            float cn = cold * ff + ii * gg2;
            float hn = tanhf(cn) * oo;
            g_cT[n * 64 + bb] = cn;
            __stcg(hTn + n * 64 + bb, hn);           // cross-CTA: bypass L1
            stash[bb * 9 + j] = hn;
        }
        __syncthreads();
        for (int i = tid; i < 384; i += NTHR) {
            int bb = i / 6, j = i - bb * 6;
            out[(size_t)bb * (T_STEPS * DIM) + (size_t)t * DIM + nb * 6 + j] =
                stash[bb * 9 + j];
        }

        grid_sync((unsigned)(t + 1) * NB_CTA);
    }
}

// ---------------------------------------------------------------------------
extern "C" void kernel_launch(void* const* d_in, const int* in_sizes, int n_in,
                              void* d_out, int out_size) {
    const float* x   = (const float*)d_in[0];
    const float* h0  = (const float*)d_in[1];
    const float* c0  = (const float*)d_in[2];
    const float* Wki = (const float*)d_in[3];
    const float* Wri = (const float*)d_in[4];
    const float* Wkf = (const float*)d_in[5];
    const float* Wrf = (const float*)d_in[6];
    const float* Wkc = (const float*)d_in[7];
    const float* Wrc = (const float*)d_in[8];
    const float* Wko = (const float*)d_in[9];
    const float* Wro = (const float*)d_in[10];
    float* out = (float*)d_out;

    cudaFuncSetAttribute(lstm_persistent,
                         cudaFuncAttributeMaxDynamicSharedMemorySize, SMEM_BYTES);

    init_state<<<192, 256>>>(h0, c0);
    transpose_wr<<<dim3(24, 24, 4), dim3(32, 8)>>>(Wri, Wrf, Wrc, Wro);
    input_proj<<<dim3(512, 6, 4), 256>>>(x, Wki, Wkf, Wkc, Wko);
    lstm_persistent<<<NB_CTA, NTHR, SMEM_BYTES>>>(out);
}

// round 17
// speedup vs baseline: 1.0231x; 1.0231x over previous
#include <cuda_runtime.h>
#include <math.h>

// Problem constants
#define T_STEPS 1024
#define BATCH   64
#define DIM     768      // D == N == 768
#define NB_CTA  128
#define NTHR    256

// -------- device-global scratch (allocation-free rule: __device__ arrays) ----
__device__ float g_xproj [(size_t)T_STEPS * 4 * BATCH * DIM];  // [t][g][b][n]
__device__ float g_xprojT[(size_t)T_STEPS * 4 * DIM * BATCH];  // [t][g][n][b]
__device__ float g_WrT[(size_t)4 * DIM * DIM];                 // [g][n][k]
__device__ float g_hT[2][DIM * BATCH];                         // [n][b] ping-pong
__device__ float g_cT[DIM * BATCH];                            // [n][b]
__device__ unsigned int g_bar;

// ---------------------------------------------------------------------------
__global__ void init_state(const float* __restrict__ h0, const float* __restrict__ c0) {
    int i = blockIdx.x * blockDim.x + threadIdx.x;
    if (i == 0) g_bar = 0u;
    if (i < DIM * BATCH) {
        int n = i >> 6, bb = i & 63;
        g_hT[0][i] = h0[bb * DIM + n];
        g_cT[i]    = c0[bb * DIM + n];
    }
}

// ---------------------------------------------------------------------------
// transpose Wr[k][n] -> g_WrT[g][n][k].  grid (24, 24, 4), block (32, 8)
// ---------------------------------------------------------------------------
__global__ void transpose_wr(const float* __restrict__ w0, const float* __restrict__ w1,
                             const float* __restrict__ w2, const float* __restrict__ w3) {
    __shared__ float tile[32][33];
    int g = blockIdx.z;
    const float* W = (g == 0) ? w0 : (g == 1) ? w1 : (g == 2) ? w2 : w3;
    int n0 = blockIdx.x * 32;
    int k0 = blockIdx.y * 32;
    int tx = threadIdx.x, ty = threadIdx.y;

    #pragma unroll
    for (int i = ty; i < 32; i += 8)
        tile[i][tx] = W[(size_t)(k0 + i) * DIM + n0 + tx];
    __syncthreads();

    float* WT = g_WrT + (size_t)g * DIM * DIM;
    #pragma unroll
    for (int i = ty; i < 32; i += 8)
        WT[(size_t)(n0 + i) * DIM + k0 + tx] = tile[tx][i];
}

// ---------------------------------------------------------------------------
// FFMA2 helper (fma.rn.f32x2 — packed 2x fp32 FMA, PTX-only on sm_103a)
// ---------------------------------------------------------------------------
__device__ __forceinline__ void ffma2(unsigned long long& d,
                                      unsigned long long a, unsigned long long b) {
    asm("fma.rn.f32x2 %0, %1, %2, %0;" : "+l"(d) : "l"(a), "l"(b));
}

// ---------------------------------------------------------------------------
// Phase 1: input projections with FFMA2 (2 m-rows packed per accumulator).
// 128x128x8 tile, 256 threads. Thread microtile: 4 row-pairs x 8 cols, both
// strided by 16 so A/B smem reads are conflict-free.
// Output layout [t][g][b][n] (coalesced float-ish stores; transposed later).
// grid (512, 6, 4)
// ---------------------------------------------------------------------------
__global__ __launch_bounds__(256) void input_proj(
        const float* __restrict__ x,
        const float* __restrict__ wk0, const float* __restrict__ wk1,
        const float* __restrict__ wk2, const float* __restrict__ wk3) {
    __shared__ __align__(16) float As[2][8][128];   // As[buf][k][m] (pairs = consecutive m)
    __shared__ __align__(16) float Bs[2][8][256];   // duplicated {w,w} per n

    int g = blockIdx.z;
    const float* W = (g == 0) ? wk0 : (g == 1) ? wk1 : (g == 2) ? wk2 : wk3;
    int m0 = blockIdx.x * 128;
    int n0 = blockIdx.y * 128;
    int tid = threadIdx.x;
    int tx = tid & 15;          // n base
    int ty = tid >> 4;          // row-pair base (0..15)

    int ar = tid >> 1, ak = (tid & 1) * 4;
    int bk = tid >> 5, bc = (tid & 31) * 4;

    const float* aptr = x + (size_t)(m0 + ar) * DIM + ak;
    const float* bptr = W + (size_t)bk * DIM + n0 + bc;

    float4 a = *(const float4*)(aptr);
    float4 b = *(const float4*)(bptr);
    As[0][ak + 0][ar] = a.x; As[0][ak + 1][ar] = a.y;
    As[0][ak + 2][ar] = a.z; As[0][ak + 3][ar] = a.w;
    *(float2*)&Bs[0][bk][2 * (bc + 0)] = make_float2(b.x, b.x);
    *(float2*)&Bs[0][bk][2 * (bc + 1)] = make_float2(b.y, b.y);
    *(float2*)&Bs[0][bk][2 * (bc + 2)] = make_float2(b.z, b.z);
    *(float2*)&Bs[0][bk][2 * (bc + 3)] = make_float2(b.w, b.w);
    __syncthreads();

    unsigned long long acc[4][8];
    #pragma unroll
    for (int i = 0; i < 4; ++i)
        #pragma unroll
        for (int j = 0; j < 8; ++j) acc[i][j] = 0ull;

    int buf = 0;
    for (int kt = 0; kt < 96; ++kt) {
        if (kt < 95) {
            int k0n = (kt + 1) * 8;
            a = *(const float4*)(aptr + k0n);
            b = *(const float4*)(bptr + (size_t)k0n * DIM);
        }
        #pragma unroll
        for (int kk = 0; kk < 8; ++kk) {
            unsigned long long a2[4], b2[8];
            #pragma unroll
            for (int i = 0; i < 4; ++i)
                a2[i] = *(const unsigned long long*)&As[buf][kk][2 * (ty + 16 * i)];
            #pragma unroll
            for (int j = 0; j < 8; ++j)
                b2[j] = *(const unsigned long long*)&Bs[buf][kk][2 * (tx + 16 * j)];
            #pragma unroll
            for (int i = 0; i < 4; ++i)
                #pragma unroll
                for (int j = 0; j < 8; ++j)
                    ffma2(acc[i][j], a2[i], b2[j]);
        }
        if (kt < 95) {
            __syncthreads();
            buf ^= 1;
            As[buf][ak + 0][ar] = a.x; As[buf][ak + 1][ar] = a.y;
            As[buf][ak + 2][ar] = a.z; As[buf][ak + 3][ar] = a.w;
            *(float2*)&Bs[buf][bk][2 * (bc + 0)] = make_float2(b.x, b.x);
            *(float2*)&Bs[buf][bk][2 * (bc + 1)] = make_float2(b.y, b.y);
            *(float2*)&Bs[buf][bk][2 * (bc + 2)] = make_float2(b.z, b.z);
            *(float2*)&Bs[buf][bk][2 * (bc + 3)] = make_float2(b.w, b.w);
            __syncthreads();
        }
    }

    // store: pair i -> rows m0+2*(ty+16i), +1 ; col j -> n0 + tx + 16j
    #pragma unroll
    for (int i = 0; i < 4; ++i) {
        int m_lo = m0 + 2 * (ty + 16 * i);
        int bb = m_lo >> 10;             // m = b*1024 + t
        int tt = m_lo & 1023;            // even; tt+1 stays in same b-block
        float* base_lo = g_xproj + ((size_t)((tt * 4 + g) * 64 + bb)) * DIM + n0;
        float* base_hi = g_xproj + ((size_t)(((tt + 1) * 4 + g) * 64 + bb)) * DIM + n0;
        #pragma unroll
        for (int j = 0; j < 8; ++j) {
            float lo, hi;
            asm("mov.b64 {%0,%1}, %2;" : "=f"(lo), "=f"(hi) : "l"(acc[i][j]));
            base_lo[tx + 16 * j] = lo;
            base_hi[tx + 16 * j] = hi;
        }
    }
}

// ---------------------------------------------------------------------------
// xproj [t][g][b][n] -> xprojT [t][g][n][b].  grid (12, 1024, 4), block 256.
// (R15 measured: direct scattered reads are 450us SLOWER than keeping this.)
// ---------------------------------------------------------------------------
__global__ __launch_bounds__(256) void transpose_x() {
    __shared__ float tile[64][65];
    int n0 = blockIdx.x * 64;
    int t  = blockIdx.y, g = blockIdx.z;
    const float* src = g_xproj  + (size_t)(t * 4 + g) * 64 * DIM;
    float*       dst = g_xprojT + (size_t)(t * 4 + g) * DIM * 64;
    int tid = threadIdx.x;
    for (int i = tid; i < 4096; i += 256) {
        int nl = i & 63, bb = i >> 6;
        tile[nl][bb] = src[(size_t)bb * DIM + n0 + nl];
    }
    __syncthreads();
    for (int i = tid; i < 4096; i += 256) {
        int bb = i & 63, nl = i >> 6;
        dst[(size_t)(n0 + nl) * 64 + bb] = tile[nl][bb];
    }
}

// ---------------------------------------------------------------------------
// Phase 2: persistent recurrence. 128 CTAs x 256 threads, 1 CTA/SM.
// Thread tile: 4 batch-pairs (8 rows) x 6 cols (one gate's 6 n-cols),
// warp-level k-split by 8 (kk === warp_kp mod 8), reduced through smem.
// h kept in [n][b] layout globally -> slice staging is a straight copy.
// Weights duplicated {w,w} in smem for the whole kernel (col pad 770 f2).
// R16 change (the ONLY change vs the R14-passing artifact): __nanosleep(64)
// in the grid_sync poll loop. Continuous RMW polling from 128 CTAs keeps the
// single-address L2 atomic queue full (~27 cyc/op serialized), so each of the
// 128 arrivals waits behind a full queue (~6-8us barrier). Throttled polling
// keeps the queue shallow -> arrivals retire in ~2us. Ordering unchanged
// (same fences, same atomic ops; polls only get slower per iteration).
// ---------------------------------------------------------------------------
#define WS_COL 770                                  // float2 per weight col (pad)
#define OFF_SCRATCH (24 * WS_COL * 2)               // 36960 floats
#define OFF_PRE     (OFF_SCRATCH + 16384)           // after 2x8192 H2 buffers
#define OFF_STASH   (OFF_PRE + 24 * 64)
#define SMEM_FLOATS (OFF_STASH + 64 * 9)
#define SMEM_BYTES  (SMEM_FLOATS * 4)               // 221824 B

__device__ __forceinline__ void grid_sync(unsigned int target) {
    __syncthreads();
    if (threadIdx.x == 0) {
        __threadfence();
        atomicAdd(&g_bar, 1u);
        while (atomicAdd(&g_bar, 0u) < target) { __nanosleep(64); }
        __threadfence();
    }
    __syncthreads();
}

__global__ __launch_bounds__(NTHR, 1) void lstm_persistent(float* __restrict__ out) {
    extern __shared__ float smem[];
    float2* Ws2    = (float2*)smem;                  // [24][WS_COL] dup weights
    float* scratch = smem + OFF_SCRATCH;             // 2x H2 buffers / red alias
    float* pre     = smem + OFF_PRE;                 // [24][64] preactivations
    float* stash   = smem + OFF_STASH;               // [64][9] h for out-writes

    const int nb  = blockIdx.x;
    const int tid = threadIdx.x;
    const int rt  = tid & 7;            // batch-pair base (pairs rt+8j)
    const int ct  = (tid >> 3) & 3;     // gate (0..3)
    const int kp  = tid >> 5;           // k-partition == warp id (0..7)

    // ---- stage duplicated weights once (reused for all 1024 steps) ----
    for (int i = tid; i < 24 * 192; i += NTHR) {
        int c = i / 192, q = i - c * 192;
        int g = c / 6, nl = c - g * 6;
        float4 v = *(const float4*)(g_WrT + ((size_t)g * DIM + nb * 6 + nl) * DIM + q * 4);
        float2* dst = Ws2 + c * WS_COL + q * 4;
        dst[0] = make_float2(v.x, v.x);
        dst[1] = make_float2(v.y, v.y);
        dst[2] = make_float2(v.z, v.z);
        dst[3] = make_float2(v.w, v.w);
    }
    __syncthreads();

    const unsigned long long* wbase =
        (const unsigned long long*)(Ws2 + ct * 6 * WS_COL);

    for (int t = 0; t < T_STEPS; ++t) {
        const float* hT = g_hT[t & 1];
        unsigned long long acc[6][4];
        #pragma unroll
        for (int cj = 0; cj < 6; ++cj)
            #pragma unroll
            for (int pj = 0; pj < 4; ++pj) acc[cj][pj] = 0ull;

        // prologue: stage k-slice 0 (straight copy — hT is [n][b])
        {
            const float4* src = (const float4*)hT;
            float4* d = (float4*)scratch;
            #pragma unroll
            for (int q = 0; q < 8; ++q) d[q * NTHR + tid] = __ldcg(src + q * NTHR + tid);
        }
        __syncthreads();

        for (int kt = 0; kt < 6; ++kt) {
            float4 r[8];
            if (kt < 5) {
                const float4* src = (const float4*)(hT + (kt + 1) * 128 * 64);
                #pragma unroll
                for (int q = 0; q < 8; ++q) r[q] = __ldcg(src + q * NTHR + tid);
            }
            const unsigned long long* h2 =
                (const unsigned long long*)(scratch + (kt & 1) * 8192);
            const int k0 = kt * 128;
            #pragma unroll 4
            for (int m = 0; m < 16; ++m) {
                int kk = kp + (m << 3);
                unsigned long long hr[4];
                #pragma unroll
                for (int pj = 0; pj < 4; ++pj)
                    hr[pj] = h2[kk * 32 + rt + (pj << 3)];
                #pragma unroll
                for (int cj = 0; cj < 6; ++cj) {
                    unsigned long long w = wbase[cj * WS_COL + k0 + kk];
                    #pragma unroll
                    for (int pj = 0; pj < 4; ++pj) ffma2(acc[cj][pj], hr[pj], w);
                }
            }
            if (kt < 5) {
                float4* d = (float4*)(scratch + ((kt + 1) & 1) * 8192);
                #pragma unroll
                for (int q = 0; q < 8; ++q) d[q * NTHR + tid] = r[q];
            }
            __syncthreads();
        }

        // ---- k-partition reduction via smem (red aliases dead H2 buffers) ----
        float2* red = (float2*)scratch;              // [8][24][33]
        #pragma unroll
        for (int cj = 0; cj < 6; ++cj)
            #pragma unroll
            for (int pj = 0; pj < 4; ++pj) {
                float lo, hi;
                asm("mov.b64 {%0,%1}, %2;" : "=f"(lo), "=f"(hi) : "l"(acc[cj][pj]));
                red[kp * 792 + (ct * 6 + cj) * 33 + rt + (pj << 3)] = make_float2(lo, hi);
            }
        __syncthreads();

        #pragma unroll
        for (int u = 0; u < 3; ++u) {
            int o = tid + u * NTHR;                  // 0..767
            int c = o >> 5, p = o & 31;
            float2 s = red[c * 33 + p];
            #pragma unroll
            for (int k2 = 1; k2 < 8; ++k2) {
                float2 v = red[k2 * 792 + c * 33 + p];
                s.x += v.x; s.y += v.y;
            }
            int g = c / 6, nl = c - g * 6;
            const float2* xp = (const float2*)(g_xprojT +
                ((size_t)((t * 4 + g) * DIM) + nb * 6 + nl) * 64);
            float2 xv = __ldg(xp + p);
            s.x += xv.x; s.y += xv.y;
            *(float2*)(pre + c * 64 + 2 * p) = s;
        }
        __syncthreads();

        // ---- gate update: 64 batch x 6 n-cols (CTA-private slice) ----
        float* hTn = g_hT[(t + 1) & 1];
        for (int i = tid; i < 384; i += NTHR) {
            int bb = i & 63, j = i >> 6;
            float xi = pre[(0 * 6 + j) * 64 + bb];
            float xf = pre[(1 * 6 + j) * 64 + bb];
            float xg = pre[(2 * 6 + j) * 64 + bb];
            float xo = pre[(3 * 6 + j) * 64 + bb];
            int n = nb * 6 + j;
            float ii  = fminf(fmaxf(0.2f * xi + 0.5f, 0.f), 1.f);
            float ff  = fminf(fmaxf(0.2f * xf + 0.5f, 0.f), 1.f);
            float oo  = fminf(fmaxf(0.2f * xo + 0.5f, 0.f), 1.f);
            float gg2 = tanhf(xg);
            float cold = g_cT[n * 64 + bb];
            float cn = cold * ff + ii * gg2;
            float hn = tanhf(cn) * oo;
            g_cT[n * 64 + bb] = cn;
            __stcg(hTn + n * 64 + bb, hn);           // cross-CTA: bypass L1
            stash[bb * 9 + j] = hn;
        }
        __syncthreads();
        for (int i = tid; i < 384; i += NTHR) {
            int bb = i / 6, j = i - bb * 6;
            out[(size_t)bb * (T_STEPS * DIM) + (size_t)t * DIM + nb * 6 + j] =
                stash[bb * 9 + j];
        }

        grid_sync((unsigned)(t + 1) * NB_CTA);
    }
}

// ---------------------------------------------------------------------------
extern "C" void kernel_launch(void* const* d_in, const int* in_sizes, int n_in,
                              void* d_out, int out_size) {
    const float* x   = (const float*)d_in[0];
    const float* h0  = (const float*)d_in[1];
    const float* c0  = (const float*)d_in[2];
    const float* Wki = (const float*)d_in[3];
    const float* Wri = (const float*)d_in[4];
    const float* Wkf = (const float*)d_in[5];
    const float* Wrf = (const float*)d_in[6];
    const float* Wkc = (const float*)d_in[7];
    const float* Wrc = (const float*)d_in[8];
    const float* Wko = (const float*)d_in[9];
    const float* Wro = (const float*)d_in[10];
    float* out = (float*)d_out;

    cudaFuncSetAttribute(lstm_persistent,
                         cudaFuncAttributeMaxDynamicSharedMemorySize, SMEM_BYTES);

    init_state<<<192, 256>>>(h0, c0);
    transpose_wr<<<dim3(24, 24, 4), dim3(32, 8)>>>(Wri, Wrf, Wrc, Wro);
    input_proj<<<dim3(512, 6, 4), 256>>>(x, Wki, Wkf, Wkc, Wko);
    transpose_x<<<dim3(12, 1024, 4), 256>>>();
    lstm_persistent<<<NB_CTA, NTHR, SMEM_BYTES>>>(out);
}